// round 2
// baseline (speedup 1.0000x reference)
#include <cuda_runtime.h>
#include <cstdint>

// x: [B, C, L, L] fp32, B=128, C=3, L=256, N=4 boxes per sample
// X/Y/W/H: [N, B] int32
// out[b,c,y,x] = inside-any-box(b,y,x) ? 0 : x[b,c,y,x]
// Mask depends on (b, y, x) only — compute once, apply to all 3 channels.

#define BB 128
#define CC 3
#define LL 256
#define NN 4

// float4s per (b) per channel: L*L/4 = 16384
#define CH4   (LL * LL / 4)          // 16384
// threads total: B * CH4 = 2,097,152  (one thread covers 3 channels)
#define TOT4  (BB * CH4)

__global__ __launch_bounds__(256)
void masking_kernel(const float4* __restrict__ x4,
                    const int* __restrict__ Xb,
                    const int* __restrict__ Yb,
                    const int* __restrict__ Wb,
                    const int* __restrict__ Hb,
                    float4* __restrict__ out4)
{
    int i4 = blockIdx.x * blockDim.x + threadIdx.x;   // [0, TOT4), exact grid

    int inner = i4 & (CH4 - 1);       // y*64 + col4 within one channel plane
    int b     = i4 >> 14;             // sample index (CH4 = 2^14)
    int col   = (i4 & 63) << 2;       // first column of this quad
    int y     = (i4 >> 6) & (LL - 1);

    long base = (long)b * (CC * CH4) + inner;

    // Front-batch all 3 channel loads (MLP_p1 = 3), streaming hint (no reuse).
    float4 v0 = __ldcs(&x4[base]);
    float4 v1 = __ldcs(&x4[base + CH4]);
    float4 v2 = __ldcs(&x4[base + 2 * CH4]);

    // 4-bit column mask for cols [col, col+3], any of N boxes.
    unsigned m = 0u;
#pragma unroll
    for (int n = 0; n < NN; n++) {
        int xs = __ldg(&Xb[n * BB + b]);
        int ys = __ldg(&Yb[n * BB + b]);
        int w  = __ldg(&Wb[n * BB + b]);
        int h  = __ldg(&Hb[n * BB + b]);
        bool yin = (y >= ys) && (y <= ys + h);
        if (yin) {
            int xe = xs + w;
#pragma unroll
            for (int j = 0; j < 4; j++) {
                int c = col + j;
                m |= ((c >= xs) & (c <= xe)) ? (1u << j) : 0u;
            }
        }
    }

    if (m & 1u) { v0.x = 0.0f; v1.x = 0.0f; v2.x = 0.0f; }
    if (m & 2u) { v0.y = 0.0f; v1.y = 0.0f; v2.y = 0.0f; }
    if (m & 4u) { v0.z = 0.0f; v1.z = 0.0f; v2.z = 0.0f; }
    if (m & 8u) { v0.w = 0.0f; v1.w = 0.0f; v2.w = 0.0f; }

    __stcs(&out4[base],           v0);
    __stcs(&out4[base + CH4],     v1);
    __stcs(&out4[base + 2 * CH4], v2);
}

extern "C" void kernel_launch(void* const* d_in, const int* in_sizes, int n_in,
                              void* d_out, int out_size)
{
    const float4* x4 = (const float4*)d_in[0];
    const int* Xb = (const int*)d_in[1];
    const int* Yb = (const int*)d_in[2];
    const int* Wb = (const int*)d_in[3];
    const int* Hb = (const int*)d_in[4];
    float4* out4 = (float4*)d_out;

    const int threads = 256;
    const int blocks = TOT4 / threads;   // 8192, exact
    masking_kernel<<<blocks, threads>>>(x4, Xb, Yb, Wb, Hb, out4);
}

// round 3
// speedup vs baseline: 1.0202x; 1.0202x over previous
#include <cuda_runtime.h>
#include <cstdint>

// x: [B, C, L, L] fp32, B=128, C=3, L=256, N=4 boxes per sample
// X/Y/W/H: [N, B] int32
// out[b,c,y,x] = inside-any-box(b,y,x) ? 0 : x[b,c,y,x]
// Mask depends on (b, y, x) only — compute once per site, apply to all 3 channels.
// Each thread handles TWO sites (i4 and i4 + TOT4/2) x 3 channels = 6 float4
// loads front-batched for deep MLP.

#define BB 128
#define CC 3
#define LL 256
#define NN 4

#define CH4   (LL * LL / 2 / 2)      // 16384 float4 per channel plane
#define TOT4  (BB * CH4)             // 2,097,152 sites
#define HALF4 (TOT4 / 2)             // 1,048,576

__device__ __forceinline__ unsigned box_mask(const int* __restrict__ Xb,
                                             const int* __restrict__ Yb,
                                             const int* __restrict__ Wb,
                                             const int* __restrict__ Hb,
                                             int b, int y, int col)
{
    unsigned m = 0u;
#pragma unroll
    for (int n = 0; n < NN; n++) {
        int xs = __ldg(&Xb[n * BB + b]);
        int ys = __ldg(&Yb[n * BB + b]);
        int w  = __ldg(&Wb[n * BB + b]);
        int h  = __ldg(&Hb[n * BB + b]);
        bool yin = (y >= ys) && (y <= ys + h);
        if (yin) {
            int xe = xs + w;
#pragma unroll
            for (int j = 0; j < 4; j++) {
                int c = col + j;
                m |= ((c >= xs) & (c <= xe)) ? (1u << j) : 0u;
            }
        }
    }
    return m;
}

__device__ __forceinline__ void apply_mask(unsigned m, float4& a, float4& b, float4& c)
{
    if (m & 1u) { a.x = 0.0f; b.x = 0.0f; c.x = 0.0f; }
    if (m & 2u) { a.y = 0.0f; b.y = 0.0f; c.y = 0.0f; }
    if (m & 4u) { a.z = 0.0f; b.z = 0.0f; c.z = 0.0f; }
    if (m & 8u) { a.w = 0.0f; b.w = 0.0f; c.w = 0.0f; }
}

__global__ __launch_bounds__(256)
void masking_kernel(const float4* __restrict__ x4,
                    const int* __restrict__ Xb,
                    const int* __restrict__ Yb,
                    const int* __restrict__ Wb,
                    const int* __restrict__ Hb,
                    float4* __restrict__ out4)
{
    int t = blockIdx.x * blockDim.x + threadIdx.x;   // [0, HALF4), exact grid

    // Site A: linear quad t;  Site B: linear quad t + HALF4 (64 samples later).
    int iA = t;
    int iB = t + HALF4;

    int innerA = iA & (CH4 - 1);
    int bA     = iA >> 14;
    int colA   = (iA & 63) << 2;
    int yA     = (iA >> 6) & (LL - 1);

    int innerB = iB & (CH4 - 1);
    int bB     = iB >> 14;
    int colB   = (iB & 63) << 2;
    int yB     = (iB >> 6) & (LL - 1);

    long baseA = (long)bA * (CC * CH4) + innerA;
    long baseB = (long)bB * (CC * CH4) + innerB;

    // Front-batch all 6 streaming loads (MLP_p1 = 6).
    float4 a0 = __ldcs(&x4[baseA]);
    float4 a1 = __ldcs(&x4[baseA + CH4]);
    float4 a2 = __ldcs(&x4[baseA + 2 * CH4]);
    float4 b0 = __ldcs(&x4[baseB]);
    float4 b1 = __ldcs(&x4[baseB + CH4]);
    float4 b2 = __ldcs(&x4[baseB + 2 * CH4]);

    unsigned mA = box_mask(Xb, Yb, Wb, Hb, bA, yA, colA);
    unsigned mB = box_mask(Xb, Yb, Wb, Hb, bB, yB, colB);

    apply_mask(mA, a0, a1, a2);
    apply_mask(mB, b0, b1, b2);

    __stcs(&out4[baseA],           a0);
    __stcs(&out4[baseA + CH4],     a1);
    __stcs(&out4[baseA + 2 * CH4], a2);
    __stcs(&out4[baseB],           b0);
    __stcs(&out4[baseB + CH4],     b1);
    __stcs(&out4[baseB + 2 * CH4], b2);
}

extern "C" void kernel_launch(void* const* d_in, const int* in_sizes, int n_in,
                              void* d_out, int out_size)
{
    const float4* x4 = (const float4*)d_in[0];
    const int* Xb = (const int*)d_in[1];
    const int* Yb = (const int*)d_in[2];
    const int* Wb = (const int*)d_in[3];
    const int* Hb = (const int*)d_in[4];
    float4* out4 = (float4*)d_out;

    const int threads = 256;
    const int blocks = HALF4 / threads;   // 4096, exact
    masking_kernel<<<blocks, threads>>>(x4, Xb, Yb, Wb, Hb, out4);
}